// round 6
// baseline (speedup 1.0000x reference)
#include <cuda_runtime.h>
#include <cstdint>

// SparseStateAggregator: B=out/65536 batches, S tokens, d=1024, M=64 states.
// 8-CTA cluster per batch, each CTA owns 128 columns of centroids+states in SMEM.
// Per token: local partial dots -> DSMEM all-gather -> redundant decision ->
// local slice update. States flushed to d_out at the end.

#define D_DIM   1024
#define M_ST    64
#define RANKS   8
#define COLS    128     // columns per CTA (D_DIM / RANKS)
#define TPB     256
#define THRESH_F 0.9f
#define EPS_F   1e-12f

// ---- shared memory layout (bytes) ----
#define OFF_MBAR   0        // 2 x u64 mbarriers (parity double buffer)
#define OFF_INTS   16       // [0]=K [1]=slot [2]=create [3]=slotprev
#define OFF_DENOM  32       // float
#define OFF_COUNTS 48       // 64 floats
#define OFF_CNORM2 304      // 64 floats
#define OFF_SQ4    560      // 4 floats (per-warp sq partials of updated row)
#define OFF_KSH    576      // 128 floats
#define OFF_VSH    1088     // 128 floats
#define OFF_RECV   1600     // float recv[2][8][66]: 0..63 dots, 64 |k|^2, 65 prev-row |c|^2
#define OFF_CENT   5824     // 64*128 floats
#define OFF_STAT   38592    // 64*128 floats
#define SMEM_BYTES 71360

static __device__ __forceinline__ uint32_t smem_u32(const void* p) {
    uint32_t a;
    asm("{ .reg .u64 t; cvta.to.shared.u64 t, %1; cvt.u32.u64 %0, t; }"
        : "=r"(a) : "l"(p));
    return a;
}

static __device__ __forceinline__ uint32_t mapa_rank(uint32_t addr, uint32_t rank) {
    uint32_t ra;
    asm("mapa.shared::cluster.u32 %0, %1, %2;" : "=r"(ra) : "r"(addr), "r"(rank));
    return ra;
}

static __device__ __forceinline__ void st_dsmem(uint32_t addr, float v) {
    asm volatile("st.shared::cluster.f32 [%0], %1;" :: "r"(addr), "f"(v) : "memory");
}

static __device__ __forceinline__ void mbar_init(uint32_t addr, uint32_t cnt) {
    asm volatile("mbarrier.init.shared.b64 [%0], %1;" :: "r"(addr), "r"(cnt) : "memory");
}

static __device__ __forceinline__ void mbar_arrive_remote(uint32_t local_mbar, uint32_t rank) {
    uint32_t ra = mapa_rank(local_mbar, rank);
    asm volatile("mbarrier.arrive.release.cluster.shared::cluster.b64 _, [%0];"
                 :: "r"(ra) : "memory");
}

static __device__ __forceinline__ void mbar_wait_cluster(uint32_t mbar, uint32_t parity) {
    asm volatile(
        "{\n\t"
        ".reg .pred P1;\n\t"
        "LAB_WAIT_%=:\n\t"
        "mbarrier.try_wait.parity.acquire.cluster.shared::cta.b64 P1, [%0], %1;\n\t"
        "@!P1 bra LAB_WAIT_%=;\n\t"
        "}\n"
        :: "r"(mbar), "r"(parity) : "memory");
}

static __device__ __forceinline__ void cluster_sync_all() {
    asm volatile("barrier.cluster.arrive.aligned;" ::: "memory");
    asm volatile("barrier.cluster.wait.aligned;" ::: "memory");
}

__global__ void __cluster_dims__(RANKS, 1, 1) __launch_bounds__(TPB, 1)
sparse_agg_kernel(const float* __restrict__ keys,
                  const float* __restrict__ values,
                  float* __restrict__ out, int S)
{
    extern __shared__ unsigned char sm[];
    const uint32_t sbase = smem_u32(sm);

    const int tid  = threadIdx.x;
    const int wid  = tid >> 5;
    const int lane = tid & 31;
    const int rank = blockIdx.x & (RANKS - 1);
    const int b    = blockIdx.x >> 3;
    const int c0   = rank * COLS;

    const float* kb = keys   + (size_t)b * S * D_DIM + c0;
    const float* vb = values + (size_t)b * S * D_DIM + c0;

    float* cent   = (float*)(sm + OFF_CENT);
    float* stat   = (float*)(sm + OFF_STAT);
    float* counts = (float*)(sm + OFF_COUNTS);
    float* cn2    = (float*)(sm + OFF_CNORM2);
    float* sq4    = (float*)(sm + OFF_SQ4);
    float* kshf   = (float*)(sm + OFF_KSH);
    float* vshf   = (float*)(sm + OFF_VSH);
    float* recvf  = (float*)(sm + OFF_RECV);
    int*   shi    = (int*)  (sm + OFF_INTS);
    float* shden  = (float*)(sm + OFF_DENOM);

    // ---- init ----
    for (int i = tid; i < M_ST * COLS; i += TPB) { cent[i] = 0.0f; stat[i] = 0.0f; }
    for (int i = tid; i < M_ST; i += TPB) { counts[i] = 0.0f; cn2[i] = 0.0f; }
    for (int i = tid; i < 2 * 8 * 66; i += TPB) recvf[i] = 0.0f;
    if (tid < 4) sq4[tid] = 0.0f;
    if (tid == 0) {
        shi[0] = 0;    // K
        shi[3] = -1;   // slotprev
        mbar_init(sbase + OFF_MBAR + 0, 56);   // 7 peers * 8 warps
        mbar_init(sbase + OFF_MBAR + 8, 56);
    }
    __syncthreads();
    cluster_sync_all();   // peers' mbarriers + recv buffers ready before any DSMEM traffic

    // prefetch token 0 (threads 0..127: k, 128..255: v)
    float pre = (tid < 128) ? kb[tid] : vb[tid - 128];

    for (int t = 0; t < S; ++t) {
        const int par = t & 1;

        // ---- stage A: publish k/v ----
        if (tid < 128) kshf[tid] = pre; else vshf[tid - 128] = pre;
        __syncthreads();

        // ---- stage B: partial dots + DSMEM all-gather ----
        {
            const float4 kq = *((const float4*)kshf + lane);
            float p[8];
            float p8 = 0.0f;
            #pragma unroll
            for (int i = 0; i < 8; ++i) {
                const float4 c4 = *((const float4*)(cent + (wid * 8 + i) * COLS) + lane);
                p[i] = kq.x * c4.x + kq.y * c4.y + kq.z * c4.z + kq.w * c4.w;
            }
            #pragma unroll
            for (int off = 16; off; off >>= 1) {
                #pragma unroll
                for (int i = 0; i < 8; ++i)
                    p[i] += __shfl_xor_sync(0xffffffffu, p[i], off);
            }
            if (wid == 0) {
                p8 = kq.x * kq.x + kq.y * kq.y + kq.z * kq.z + kq.w * kq.w;
                #pragma unroll
                for (int off = 16; off; off >>= 1)
                    p8 += __shfl_xor_sync(0xffffffffu, p8, off);
            }
            // lane r (< 8) ships this warp's values to CTA r, then arrives there.
            if (lane < 8) {
                const int r = lane;
                float sqs = 0.0f;
                if (wid == 0) sqs = sq4[0] + sq4[1] + sq4[2] + sq4[3];
                const int base_idx = (par * 8 + rank) * 66 + wid * 8;
                if (r == rank) {
                    float* dst = recvf + base_idx;
                    #pragma unroll
                    for (int i = 0; i < 8; ++i) dst[i] = p[i];
                    if (wid == 0) { dst[64] = p8; dst[65] = sqs; }
                } else {
                    const uint32_t loff = sbase + OFF_RECV + (uint32_t)(base_idx * 4);
                    const uint32_t ra = mapa_rank(loff, (uint32_t)r);
                    #pragma unroll
                    for (int i = 0; i < 8; ++i) st_dsmem(ra + 4u * i, p[i]);
                    if (wid == 0) {
                        st_dsmem(ra + 4u * 64, p8);
                        st_dsmem(ra + 4u * 65, sqs);
                    }
                    mbar_arrive_remote(sbase + OFF_MBAR + (uint32_t)(par * 8), (uint32_t)r);
                }
            }
        }

        // ---- stage C: prefetch next token (hides exchange latency) ----
        float nxt = 0.0f;
        if (t + 1 < S)
            nxt = (tid < 128) ? kb[(size_t)(t + 1) * D_DIM + tid]
                              : vb[(size_t)(t + 1) * D_DIM + (tid - 128)];
        __syncthreads();   // local recv stores visible to warp 0

        // ---- stage D: warp 0 waits + decides (bit-identical across all CTAs) ----
        if (wid == 0) {
            mbar_wait_cluster(sbase + OFF_MBAR + (uint32_t)(par * 8),
                              (uint32_t)((t >> 1) & 1));
            const float* rcv = recvf + par * 8 * 66;
            if (lane == 0) {
                const int sp = shi[3];
                if (sp >= 0) {   // refresh exact ||stored centroid||^2 of last-updated row
                    float s = 0.0f;
                    #pragma unroll
                    for (int r = 0; r < 8; ++r) s += rcv[r * 66 + 65];
                    cn2[sp] = s;
                }
            }
            __syncwarp();
            float kn2 = 0.0f;
            #pragma unroll
            for (int r = 0; r < 8; ++r) kn2 += rcv[r * 66 + 64];
            const float rk = rsqrtf(kn2 + EPS_F);
            const int s1 = lane, s2 = lane + 32;
            float d1 = 0.0f, d2 = 0.0f;
            #pragma unroll
            for (int r = 0; r < 8; ++r) { d1 += rcv[r * 66 + s1]; d2 += rcv[r * 66 + s2]; }
            const float v1 = (counts[s1] > 0.0f) ? d1 * rsqrtf(cn2[s1] + EPS_F) * rk : -3.0e38f;
            const float v2 = (counts[s2] > 0.0f) ? d2 * rsqrtf(cn2[s2] + EPS_F) * rk : -3.0e38f;
            float bv; int bi;
            if (v2 > v1) { bv = v2; bi = s2; } else { bv = v1; bi = s1; }
            #pragma unroll
            for (int off = 16; off; off >>= 1) {   // argmax, first-index tiebreak
                const float ov = __shfl_xor_sync(0xffffffffu, bv, off);
                const int   oi = __shfl_xor_sync(0xffffffffu, bi, off);
                if (ov > bv || (ov == bv && oi < bi)) { bv = ov; bi = oi; }
            }
            if (lane == 0) {
                const int K = shi[0];
                const int create = (K == 0) || (bv < THRESH_F && K < M_ST);
                const int slot = create ? K : bi;
                const float n = counts[slot];
                counts[slot] = create ? 1.0f : (n + 1.0f);
                shi[0] = K + create;
                shi[1] = slot;
                shi[2] = create;
                shi[3] = slot;
                *shden = n + 1.0f;
            }
        }
        __syncthreads();

        // ---- stage E: update owned slice of centroid + state rows ----
        {
            const int slot = shi[1];
            const int create = shi[2];
            const float denom = *shden;
            if (tid < 128) {
                const float c = cent[slot * COLS + tid];
                const float k = kshf[tid];
                const float nc = create ? k : (c + (k - c) / denom);
                cent[slot * COLS + tid] = nc;
                float sq = nc * nc;
                #pragma unroll
                for (int off = 16; off; off >>= 1)
                    sq += __shfl_xor_sync(0xffffffffu, sq, off);
                if (lane == 0) sq4[wid] = sq;
            } else {
                const int j = tid - 128;
                const float s = stat[slot * COLS + j];
                const float v = vshf[j];
                stat[slot * COLS + j] = create ? v : (s + (v - s) / denom);
            }
        }
        pre = nxt;
        __syncthreads();
    }

    // ---- flush states (== output) ----
    {
        const int half = tid >> 7;
        const int j = tid & 127;
        float* ob = out + (size_t)b * M_ST * D_DIM + c0;
        for (int s = half * 32; s < half * 32 + 32; ++s)
            ob[(size_t)s * D_DIM + j] = stat[s * COLS + j];
    }
    cluster_sync_all();   // keep SMEM alive until all peers' remote ops settle
}

extern "C" void kernel_launch(void* const* d_in, const int* in_sizes, int n_in,
                              void* d_out, int out_size) {
    const float* keys   = (const float*)d_in[0];
    const float* values = (const float*)d_in[1];
    float* out = (float*)d_out;

    const int B = out_size / (M_ST * D_DIM);
    const int S = in_sizes[0] / (B * D_DIM);

    cudaFuncSetAttribute(sparse_agg_kernel,
                         cudaFuncAttributeMaxDynamicSharedMemorySize, SMEM_BYTES);
    sparse_agg_kernel<<<B * RANKS, TPB, SMEM_BYTES>>>(keys, values, out, S);
}